// round 1
// baseline (speedup 1.0000x reference)
#include <cuda_runtime.h>
#include <math.h>

// Problem dims
#define NB 2
#define NT 2048
#define NC 1024
#define NH 16
#define ND 64
#define MTOT (NB*NT)   // 4096

// Scratch (device globals: no allocation allowed in kernel_launch)
__device__ float g_q[NB*NH*NT*ND];
__device__ float g_k[NB*NH*NT*ND];
__device__ float g_v[NB*NH*NT*ND];
__device__ float g_y[NB*NT*NC];

// ---------------------------------------------------------------------------
// Tiled NT GEMM: out[m,n] = sum_k A[m,k] * W[n,k]  (+bias at store time)
// A: [M, NC] row-major, W: [N, NC] row-major. BM=BN=64, BK=16, 256 threads,
// 4x4 microtile per thread. Both tiles transposed to [BK][pad] in smem so the
// inner loop reads conflict-free float4s.
// ---------------------------------------------------------------------------
#define BM 64
#define BN 64
#define BK 16
#define GP 68  // padded smem row (floats); 68*4B = 272B keeps 16B alignment

__device__ __forceinline__ void gemm_nt_tile(const float* __restrict__ A,
                                             const float* __restrict__ W,
                                             float acc[4][4])
{
    __shared__ float As[BK][GP];
    __shared__ float Bs[BK][GP];
    const int tid = threadIdx.x;
    const int tx  = tid & 15;
    const int ty  = tid >> 4;
    const int lr  = tid >> 2;        // 0..63: row of the 64-row tile to load
    const int lk  = (tid & 3) << 2;  // 0,4,8,12: k offset within BK
    const int m0  = blockIdx.y * BM;
    const int n0  = blockIdx.x * BN;

    const float* ap = A + (size_t)(m0 + lr) * NC + lk;
    const float* bp = W + (size_t)(n0 + lr) * NC + lk;

    for (int k0 = 0; k0 < NC; k0 += BK) {
        float4 av = *(const float4*)(ap + k0);
        float4 bv = *(const float4*)(bp + k0);
        __syncthreads();   // previous iteration's reads done
        As[lk+0][lr] = av.x; As[lk+1][lr] = av.y;
        As[lk+2][lr] = av.z; As[lk+3][lr] = av.w;
        Bs[lk+0][lr] = bv.x; Bs[lk+1][lr] = bv.y;
        Bs[lk+2][lr] = bv.z; Bs[lk+3][lr] = bv.w;
        __syncthreads();
        #pragma unroll
        for (int k = 0; k < BK; k++) {
            float4 ra = *(const float4*)&As[k][ty << 2];
            float4 rb = *(const float4*)&Bs[k][tx << 2];
            float a_[4] = {ra.x, ra.y, ra.z, ra.w};
            float b_[4] = {rb.x, rb.y, rb.z, rb.w};
            #pragma unroll
            for (int i = 0; i < 4; i++)
                #pragma unroll
                for (int j = 0; j < 4; j++)
                    acc[i][j] = fmaf(a_[i], b_[j], acc[i][j]);
        }
    }
}

// QKV projections fused via gridDim.z; writes head-split [B, H, T, 64]
__global__ __launch_bounds__(256)
void qkv_kernel(const float* __restrict__ x,
                const float* __restrict__ Wq, const float* __restrict__ bq,
                const float* __restrict__ Wk, const float* __restrict__ bk,
                const float* __restrict__ Wv, const float* __restrict__ bv)
{
    const float* W; const float* bias; float* Out;
    if (blockIdx.z == 0)      { W = Wq; bias = bq; Out = g_q; }
    else if (blockIdx.z == 1) { W = Wk; bias = bk; Out = g_k; }
    else                      { W = Wv; bias = bv; Out = g_v; }

    float acc[4][4] = {};
    gemm_nt_tile(x, W, acc);

    const int tid = threadIdx.x;
    const int tx  = tid & 15;
    const int ty  = tid >> 4;
    const int mb  = blockIdx.y * BM + (ty << 2);
    const int nb  = blockIdx.x * BN + (tx << 2);
    #pragma unroll
    for (int i = 0; i < 4; i++) {
        const int m = mb + i;
        const int b = m >> 11;          // T = 2048
        const int t = m & (NT - 1);
        #pragma unroll
        for (int j = 0; j < 4; j++) {
            const int n  = nb + j;
            const int h  = n >> 6;      // HD = 64
            const int hd = n & 63;
            Out[(((size_t)(b * NH + h)) * NT + t) * ND + hd] = acc[i][j] + bias[n];
        }
    }
}

// Output projection: g_y @ Wp.T + bp -> d_out, flat [B,T,C]
__global__ __launch_bounds__(256)
void proj_kernel(const float* __restrict__ Wp, const float* __restrict__ bp,
                 float* __restrict__ out)
{
    float acc[4][4] = {};
    gemm_nt_tile(g_y, Wp, acc);

    const int tid = threadIdx.x;
    const int tx  = tid & 15;
    const int ty  = tid >> 4;
    const int mb  = blockIdx.y * BM + (ty << 2);
    const int nb  = blockIdx.x * BN + (tx << 2);
    #pragma unroll
    for (int i = 0; i < 4; i++) {
        const int m = mb + i;
        #pragma unroll
        for (int j = 0; j < 4; j++) {
            const int n = nb + j;
            out[(size_t)m * NC + n] = acc[i][j] + bp[n];
        }
    }
}

// ---------------------------------------------------------------------------
// Flash attention, causal, fp32. One thread per query row: q[64] and o[64]
// live entirely in registers, so the online softmax needs no cross-thread
// reduction. K/V tiles (64 keys x 64 dims) staged in smem via contiguous
// float4 copies. Lazy rescale: only when the running max changes.
// ---------------------------------------------------------------------------
#define AR 64   // query rows per block == threads per block

__global__ __launch_bounds__(AR)
void attn_kernel()
{
    __shared__ float Ks[AR * ND];
    __shared__ float Vs[AR * ND];

    const int bh   = blockIdx.y;                      // 0..B*H-1
    const int qb   = gridDim.x - 1 - blockIdx.x;      // heavy blocks first
    const int tid  = threadIdx.x;
    const int qrow = qb * AR + tid;

    const float* qp = g_q + ((size_t)bh * NT + qrow) * ND;
    float q[ND];
    #pragma unroll
    for (int i = 0; i < 16; i++) {
        float4 v = ((const float4*)qp)[i];
        q[4*i+0] = v.x * 0.125f;   // pre-scale by 1/sqrt(64)
        q[4*i+1] = v.y * 0.125f;
        q[4*i+2] = v.z * 0.125f;
        q[4*i+3] = v.w * 0.125f;
    }
    float o[ND];
    #pragma unroll
    for (int d = 0; d < ND; d++) o[d] = 0.f;
    float mval = -1e30f;
    float lsum = 0.f;

    const float4* kb = (const float4*)(g_k + (size_t)bh * NT * ND);
    const float4* vb = (const float4*)(g_v + (size_t)bh * NT * ND);
    const int ntiles = qb + 1;

    for (int kt = 0; kt < ntiles; kt++) {
        __syncthreads();
        // Tile is a contiguous 16KB chunk: 1024 float4s, 16 per thread
        #pragma unroll
        for (int i = 0; i < 16; i++) {
            ((float4*)Ks)[tid + i * AR] = kb[kt * 1024 + tid + i * AR];
            ((float4*)Vs)[tid + i * AR] = vb[kt * 1024 + tid + i * AR];
        }
        __syncthreads();

        const int jmax = min(AR, qrow - kt * AR + 1);  // causal bound; >=1
        for (int j = 0; j < jmax; j++) {
            const float4* kr = (const float4*)(Ks + j * ND);
            float s0 = 0.f, s1 = 0.f, s2 = 0.f, s3 = 0.f;
            #pragma unroll
            for (int d4 = 0; d4 < 16; d4++) {
                float4 kk = kr[d4];
                s0 = fmaf(q[4*d4+0], kk.x, s0);
                s1 = fmaf(q[4*d4+1], kk.y, s1);
                s2 = fmaf(q[4*d4+2], kk.z, s2);
                s3 = fmaf(q[4*d4+3], kk.w, s3);
            }
            const float s = (s0 + s1) + (s2 + s3);
            if (s > mval) {
                const float corr = __expf(mval - s);
                lsum *= corr;
                #pragma unroll
                for (int d = 0; d < ND; d++) o[d] *= corr;
                mval = s;
            }
            const float p = __expf(s - mval);
            lsum += p;
            const float4* vr = (const float4*)(Vs + j * ND);
            #pragma unroll
            for (int d4 = 0; d4 < 16; d4++) {
                float4 vv = vr[d4];
                o[4*d4+0] = fmaf(p, vv.x, o[4*d4+0]);
                o[4*d4+1] = fmaf(p, vv.y, o[4*d4+1]);
                o[4*d4+2] = fmaf(p, vv.z, o[4*d4+2]);
                o[4*d4+3] = fmaf(p, vv.w, o[4*d4+3]);
            }
        }
    }

    const float inv = 1.0f / lsum;
    const int b = bh >> 4;   // H = 16
    const int h = bh & 15;
    float* yp = g_y + ((size_t)(b * NT + qrow)) * NC + h * ND;
    #pragma unroll
    for (int d4 = 0; d4 < 16; d4++) {
        float4 w;
        w.x = o[4*d4+0] * inv;
        w.y = o[4*d4+1] * inv;
        w.z = o[4*d4+2] * inv;
        w.w = o[4*d4+3] * inv;
        ((float4*)yp)[d4] = w;
    }
}

// ---------------------------------------------------------------------------
extern "C" void kernel_launch(void* const* d_in, const int* in_sizes, int n_in,
                              void* d_out, int out_size)
{
    const float* x  = (const float*)d_in[0];
    const float* Wk = (const float*)d_in[1];
    const float* bk = (const float*)d_in[2];
    const float* Wq = (const float*)d_in[3];
    const float* bq = (const float*)d_in[4];
    const float* Wv = (const float*)d_in[5];
    const float* bv = (const float*)d_in[6];
    const float* Wp = (const float*)d_in[7];
    const float* bp = (const float*)d_in[8];
    float* out = (float*)d_out;

    dim3 gq(NC / BN, MTOT / BM, 3);
    qkv_kernel<<<gq, 256>>>(x, Wq, bq, Wk, bk, Wv, bv);

    dim3 ga(NT / AR, NB * NH);
    attn_kernel<<<ga, AR>>>();

    dim3 gp(NC / BN, MTOT / BM);
    proj_kernel<<<gp, 256>>>(Wp, bp, out);
}

// round 3
// speedup vs baseline: 2.8208x; 2.8208x over previous
#include <cuda_runtime.h>
#include <math.h>

#define NB 2
#define NT 2048
#define NC 1024
#define NH 16
#define ND 64
#define MTOT (NB*NT)   // 4096

// Scratch
__device__ float g_q[NB*NH*NT*ND];
__device__ float g_k[NB*NH*NT*ND];
__device__ float g_v[NB*NH*NT*ND];
__device__ float g_y[NB*NT*NC];

__device__ __forceinline__ unsigned f2tf(float f) {
    unsigned r;
    asm("cvt.rna.tf32.f32 %0, %1;" : "=r"(r) : "f"(f));
    return r;
}

__device__ __forceinline__ void mma_tf32(float c[4], unsigned a0, unsigned a1,
                                         unsigned a2, unsigned a3,
                                         unsigned b0, unsigned b1)
{
    asm volatile(
        "mma.sync.aligned.m16n8k8.row.col.f32.tf32.tf32.f32 "
        "{%0,%1,%2,%3}, {%4,%5,%6,%7}, {%8,%9}, {%0,%1,%2,%3};"
        : "+f"(c[0]), "+f"(c[1]), "+f"(c[2]), "+f"(c[3])
        : "r"(a0), "r"(a1), "r"(a2), "r"(a3), "r"(b0), "r"(b1));
}

// ---------------------------------------------------------------------------
// TF32 tensor-core NT GEMM: out[m,n] = sum_k A[m,k]*W[n,k]
// Block 256 threads (8 warps, 4x2), tile 128x64, BK=32.
// Fragments (m16n8k8 tf32): a0=(g,t) a1=(g+8,t) a2=(g,t+4) a3=(g+8,t+4);
// b0=(k=t,n=g) b1=(k=t+4,n=g); c0=(g,2t) c1=(g,2t+1) c2=(g+8,2t) c3=(g+8,2t+1)
// ---------------------------------------------------------------------------
#define GBM 128
#define GBN 64
#define GBK 32
#define GSA 36   // smem row stride (uints): (r*36+c)%32 = (4r+c)%32 -> conflict-free frags

__device__ __forceinline__ void gemm_tc(const float* __restrict__ A,
                                        const float* __restrict__ W,
                                        float C[2][4][4], int m0, int n0)
{
    __shared__ unsigned As[GBM * GSA];
    __shared__ unsigned Ws[GBN * GSA];

    const int tid  = threadIdx.x;
    const int wid  = tid >> 5;
    const int lane = tid & 31;
    const int g    = lane >> 2;
    const int t    = lane & 3;
    const int wr   = wid >> 1;   // 0..3 -> m offset wr*32
    const int wc   = wid & 1;    // 0..1 -> n offset wc*32

    const int ar  = tid >> 3;    // 0..31 (+ i*32)
    const int ac4 = tid & 7;     // float4 column

    const float* Aptr = A + (size_t)(m0 + ar) * NC + ac4 * 4;
    const float* Wptr = W + (size_t)(n0 + ar) * NC + ac4 * 4;

    float4 afetch[4], wfetch[2];
    #pragma unroll
    for (int i = 0; i < 4; i++) afetch[i] = *(const float4*)(Aptr + i * 32 * NC);
    #pragma unroll
    for (int i = 0; i < 2; i++) wfetch[i] = *(const float4*)(Wptr + i * 32 * NC);

    for (int k0 = 0; k0 < NC; k0 += GBK) {
        __syncthreads();
        #pragma unroll
        for (int i = 0; i < 4; i++) {
            uint4 u;
            u.x = f2tf(afetch[i].x); u.y = f2tf(afetch[i].y);
            u.z = f2tf(afetch[i].z); u.w = f2tf(afetch[i].w);
            *(uint4*)&As[(ar + i * 32) * GSA + ac4 * 4] = u;
        }
        #pragma unroll
        for (int i = 0; i < 2; i++) {
            uint4 u;
            u.x = f2tf(wfetch[i].x); u.y = f2tf(wfetch[i].y);
            u.z = f2tf(wfetch[i].z); u.w = f2tf(wfetch[i].w);
            *(uint4*)&Ws[(ar + i * 32) * GSA + ac4 * 4] = u;
        }
        __syncthreads();

        if (k0 + GBK < NC) {   // prefetch next tile while computing this one
            #pragma unroll
            for (int i = 0; i < 4; i++)
                afetch[i] = *(const float4*)(Aptr + i * 32 * NC + k0 + GBK);
            #pragma unroll
            for (int i = 0; i < 2; i++)
                wfetch[i] = *(const float4*)(Wptr + i * 32 * NC + k0 + GBK);
        }

        #pragma unroll
        for (int kk = 0; kk < GBK; kk += 8) {
            unsigned a[2][4], b[4][2];
            #pragma unroll
            for (int mt = 0; mt < 2; mt++) {
                const int r = wr * 32 + mt * 16;
                a[mt][0] = As[(r + g)     * GSA + kk + t];
                a[mt][1] = As[(r + g + 8) * GSA + kk + t];
                a[mt][2] = As[(r + g)     * GSA + kk + t + 4];
                a[mt][3] = As[(r + g + 8) * GSA + kk + t + 4];
            }
            #pragma unroll
            for (int nt = 0; nt < 4; nt++) {
                const int c = wc * 32 + nt * 8;
                b[nt][0] = Ws[(c + g) * GSA + kk + t];
                b[nt][1] = Ws[(c + g) * GSA + kk + t + 4];
            }
            #pragma unroll
            for (int mt = 0; mt < 2; mt++)
                #pragma unroll
                for (int nt = 0; nt < 4; nt++)
                    mma_tf32(C[mt][nt], a[mt][0], a[mt][1], a[mt][2], a[mt][3],
                             b[nt][0], b[nt][1]);
        }
    }
}

// QKV projections (gridDim.z selects Q/K/V), head-split scatter store
__global__ __launch_bounds__(256)
void qkv_kernel(const float* __restrict__ x,
                const float* __restrict__ Wq, const float* __restrict__ bq,
                const float* __restrict__ Wk, const float* __restrict__ bk,
                const float* __restrict__ Wv, const float* __restrict__ bv)
{
    const float* W; const float* bias; float* Out;
    if (blockIdx.z == 0)      { W = Wq; bias = bq; Out = g_q; }
    else if (blockIdx.z == 1) { W = Wk; bias = bk; Out = g_k; }
    else                      { W = Wv; bias = bv; Out = g_v; }

    const int m0 = blockIdx.y * GBM;
    const int n0 = blockIdx.x * GBN;
    float C[2][4][4] = {};
    gemm_tc(x, W, C, m0, n0);

    const int lane = threadIdx.x & 31, wid = threadIdx.x >> 5;
    const int g = lane >> 2, t = lane & 3;
    const int wr = wid >> 1, wc = wid & 1;
    const int h = n0 >> 6;               // GBN==64 == one head

    #pragma unroll
    for (int mt = 0; mt < 2; mt++) {
        #pragma unroll
        for (int rr = 0; rr < 2; rr++) {
            const int m = m0 + wr * 32 + mt * 16 + g + rr * 8;
            const int b = m >> 11;
            const int tt = m & (NT - 1);
            float* op = Out + (((size_t)(b * NH + h)) * NT + tt) * ND;
            #pragma unroll
            for (int nt = 0; nt < 4; nt++) {
                const int nl = wc * 32 + nt * 8 + 2 * t;   // hd within head
                float2 v;
                v.x = C[mt][nt][rr * 2 + 0] + bias[n0 + nl];
                v.y = C[mt][nt][rr * 2 + 1] + bias[n0 + nl + 1];
                *(float2*)(op + nl) = v;
            }
        }
    }
}

// Output projection: g_y @ Wp.T + bp -> d_out
__global__ __launch_bounds__(256)
void proj_kernel(const float* __restrict__ Wp, const float* __restrict__ bp,
                 float* __restrict__ out)
{
    const int m0 = blockIdx.y * GBM;
    const int n0 = blockIdx.x * GBN;
    float C[2][4][4] = {};
    gemm_tc(g_y, Wp, C, m0, n0);

    const int lane = threadIdx.x & 31, wid = threadIdx.x >> 5;
    const int g = lane >> 2, t = lane & 3;
    const int wr = wid >> 1, wc = wid & 1;

    #pragma unroll
    for (int mt = 0; mt < 2; mt++) {
        #pragma unroll
        for (int rr = 0; rr < 2; rr++) {
            const int m = m0 + wr * 32 + mt * 16 + g + rr * 8;
            #pragma unroll
            for (int nt = 0; nt < 4; nt++) {
                const int n = n0 + wc * 32 + nt * 8 + 2 * t;
                float2 v;
                v.x = C[mt][nt][rr * 2 + 0] + bp[n];
                v.y = C[mt][nt][rr * 2 + 1] + bp[n + 1];
                *(float2*)(out + (size_t)m * NC + n) = v;
            }
        }
    }
}

// ---------------------------------------------------------------------------
// Tensor-core flash attention, causal. Block = 128 threads (4 warps),
// 64 query rows per block (16 per warp). S = Q K^T via tf32 mma, fp32 online
// softmax on C-fragments, P routed through smem (K-tile region) to A-frags,
// O += P V via tf32 mma.
// smem pad 72: bank index (r*72+c)%32 = (8r+c)%32 -> conflict-free for all
// fragment access patterns used below.
// ---------------------------------------------------------------------------
#define APAD 72

__global__ __launch_bounds__(128)
void attn_kernel()
{
    __shared__ unsigned Ks[64 * APAD];  // K tile (tf32), reused for Q stage + P
    __shared__ unsigned Vs[64 * APAD];  // V tile (tf32)

    const int tid  = threadIdx.x;
    const int wid  = tid >> 5;
    const int lane = tid & 31;
    const int g    = lane >> 2;
    const int t    = lane & 3;

    const int bh = blockIdx.y;
    const int qb = gridDim.x - 1 - blockIdx.x;   // heavy blocks first
    const int q0 = qb * 64;

    // ---- Stage Q (pre-scaled by 1/8, tf32) and read A-fragments ----
    {
        const float* qbase = g_q + ((size_t)bh * NT + q0) * ND;
        const int row = wid * 16 + (lane >> 1);        // 16 rows per warp
        const int c0  = (lane & 1) * 8;                // 8 float4 each
        #pragma unroll
        for (int i = 0; i < 8; i++) {
            float4 v = *(const float4*)(qbase + row * ND + (c0 + i) * 4);
            uint4 u;
            u.x = f2tf(v.x * 0.125f); u.y = f2tf(v.y * 0.125f);
            u.z = f2tf(v.z * 0.125f); u.w = f2tf(v.w * 0.125f);
            *(uint4*)&Ks[row * APAD + (c0 + i) * 4] = u;
        }
    }
    __syncthreads();

    unsigned Qf[8][4];
    {
        const int r = wid * 16;
        #pragma unroll
        for (int kt = 0; kt < 8; kt++) {
            Qf[kt][0] = Ks[(r + g)     * APAD + kt * 8 + t];
            Qf[kt][1] = Ks[(r + g + 8) * APAD + kt * 8 + t];
            Qf[kt][2] = Ks[(r + g)     * APAD + kt * 8 + t + 4];
            Qf[kt][3] = Ks[(r + g + 8) * APAD + kt * 8 + t + 4];
        }
    }
    __syncthreads();   // Q reads done before Ks becomes the K tile

    float Of[8][4];
    #pragma unroll
    for (int nt = 0; nt < 8; nt++)
        #pragma unroll
        for (int j = 0; j < 4; j++) Of[nt][j] = 0.f;
    float mrow[2] = {-1e30f, -1e30f};
    float lrow[2] = {0.f, 0.f};

    const float* kbase = g_k + (size_t)bh * NT * ND;
    const float* vbase = g_v + (size_t)bh * NT * ND;

    const int lrw = tid >> 1;            // 0..63: K/V row to stage
    const int lc0 = (tid & 1) * 8;

    for (int kt0 = 0; kt0 <= qb; kt0++) {
        // stage K and V tiles (tf32)
        #pragma unroll
        for (int i = 0; i < 8; i++) {
            float4 kv = *(const float4*)(kbase + ((size_t)(kt0 * 64 + lrw)) * ND + (lc0 + i) * 4);
            uint4 u;
            u.x = f2tf(kv.x); u.y = f2tf(kv.y); u.z = f2tf(kv.z); u.w = f2tf(kv.w);
            *(uint4*)&Ks[lrw * APAD + (lc0 + i) * 4] = u;
            float4 vv = *(const float4*)(vbase + ((size_t)(kt0 * 64 + lrw)) * ND + (lc0 + i) * 4);
            uint4 w;
            w.x = f2tf(vv.x); w.y = f2tf(vv.y); w.z = f2tf(vv.z); w.w = f2tf(vv.w);
            *(uint4*)&Vs[lrw * APAD + (lc0 + i) * 4] = w;
        }
        __syncthreads();

        // S = Q K^T  (16 rows x 64 keys per warp)
        float Sf[8][4];
        #pragma unroll
        for (int nt = 0; nt < 8; nt++)
            #pragma unroll
            for (int j = 0; j < 4; j++) Sf[nt][j] = 0.f;

        #pragma unroll
        for (int kt = 0; kt < 8; kt++) {
            #pragma unroll
            for (int nt = 0; nt < 8; nt++) {
                unsigned b0 = Ks[(nt * 8 + g) * APAD + kt * 8 + t];
                unsigned b1 = Ks[(nt * 8 + g) * APAD + kt * 8 + t + 4];
                mma_tf32(Sf[nt], Qf[kt][0], Qf[kt][1], Qf[kt][2], Qf[kt][3], b0, b1);
            }
        }

        // causal mask on the diagonal tile
        if (kt0 == qb) {
            #pragma unroll
            for (int nt = 0; nt < 8; nt++)
                #pragma unroll
                for (int j = 0; j < 4; j++) {
                    const int key = nt * 8 + 2 * t + (j & 1);
                    const int qr  = wid * 16 + g + (j >> 1) * 8;
                    if (key > qr) Sf[nt][j] = -1e30f;
                }
        }

        // online softmax (two rows per thread: g and g+8)
        #pragma unroll
        for (int r = 0; r < 2; r++) {
            float rm = -1e30f;
            #pragma unroll
            for (int nt = 0; nt < 8; nt++) {
                rm = fmaxf(rm, Sf[nt][2 * r]);
                rm = fmaxf(rm, Sf[nt][2 * r + 1]);
            }
            rm = fmaxf(rm, __shfl_xor_sync(0xffffffff, rm, 1));
            rm = fmaxf(rm, __shfl_xor_sync(0xffffffff, rm, 2));
            const float mn   = fmaxf(mrow[r], rm);
            const float corr = __expf(mrow[r] - mn);
            mrow[r] = mn;
            float rs = 0.f;
            #pragma unroll
            for (int nt = 0; nt < 8; nt++) {
                const float p0 = __expf(Sf[nt][2 * r]     - mn);
                const float p1 = __expf(Sf[nt][2 * r + 1] - mn);
                Sf[nt][2 * r] = p0; Sf[nt][2 * r + 1] = p1;
                rs += p0 + p1;
            }
            rs += __shfl_xor_sync(0xffffffff, rs, 1);
            rs += __shfl_xor_sync(0xffffffff, rs, 2);
            lrow[r] = lrow[r] * corr + rs;
            #pragma unroll
            for (int nt = 0; nt < 8; nt++) {
                Of[nt][2 * r]     *= corr;
                Of[nt][2 * r + 1] *= corr;
            }
        }

        __syncthreads();    // all warps done reading Ks -> reuse it for P

        // write P (tf32) into this warp's 16-row slice of Ks
        unsigned* Pw = Ks + wid * 16 * APAD;
        #pragma unroll
        for (int nt = 0; nt < 8; nt++)
            #pragma unroll
            for (int j = 0; j < 4; j++)
                Pw[(g + (j >> 1) * 8) * APAD + nt * 8 + 2 * t + (j & 1)] = f2tf(Sf[nt][j]);
        __syncwarp();

        // O += P V
        #pragma unroll
        for (int kt = 0; kt < 8; kt++) {
            const unsigned a0 = Pw[(g)     * APAD + kt * 8 + t];
            const unsigned a1 = Pw[(g + 8) * APAD + kt * 8 + t];
            const unsigned a2 = Pw[(g)     * APAD + kt * 8 + t + 4];
            const unsigned a3 = Pw[(g + 8) * APAD + kt * 8 + t + 4];
            #pragma unroll
            for (int nt = 0; nt < 8; nt++) {
                unsigned b0 = Vs[(kt * 8 + t)     * APAD + nt * 8 + g];
                unsigned b1 = Vs[(kt * 8 + t + 4) * APAD + nt * 8 + g];
                mma_tf32(Of[nt], a0, a1, a2, a3, b0, b1);
            }
        }
        __syncthreads();    // P/V reads done before next tile overwrites
    }

    // epilogue: divide by l, scatter to g_y [b, t, h*64 + d]
    const float inv0 = 1.0f / lrow[0];
    const float inv1 = 1.0f / lrow[1];
    const int b = bh >> 4;
    const int h = bh & 15;
    float* yp = g_y + ((size_t)(b * NT) + q0) * NC + h * ND;

    #pragma unroll
    for (int nt = 0; nt < 8; nt++) {
        const int c = nt * 8 + 2 * t;
        const int r0 = wid * 16 + g;
        float2 v0; v0.x = Of[nt][0] * inv0; v0.y = Of[nt][1] * inv0;
        *(float2*)(yp + (size_t)r0 * NC + c) = v0;
        float2 v1; v1.x = Of[nt][2] * inv1; v1.y = Of[nt][3] * inv1;
        *(float2*)(yp + (size_t)(r0 + 8) * NC + c) = v1;
    }
}

// ---------------------------------------------------------------------------
extern "C" void kernel_launch(void* const* d_in, const int* in_sizes, int n_in,
                              void* d_out, int out_size)
{
    const float* x  = (const float*)d_in[0];
    const float* Wk = (const float*)d_in[1];
    const float* bk = (const float*)d_in[2];
    const float* Wq = (const float*)d_in[3];
    const float* bq = (const float*)d_in[4];
    const float* Wv = (const float*)d_in[5];
    const float* bv = (const float*)d_in[6];
    const float* Wp = (const float*)d_in[7];
    const float* bp = (const float*)d_in[8];
    float* out = (float*)d_out;

    dim3 gq(NC / GBN, MTOT / GBM, 3);
    qkv_kernel<<<gq, 256>>>(x, Wq, bq, Wk, bk, Wv, bv);

    dim3 ga(NT / 64, NB * NH);
    attn_kernel<<<ga, 128>>>();

    dim3 gp(NC / GBN, MTOT / GBM);
    proj_kernel<<<gp, 256>>>(Wp, bp, out);
}

// round 4
// speedup vs baseline: 3.5150x; 1.2461x over previous
#include <cuda_runtime.h>
#include <math.h>

#define NB 2
#define NT 2048
#define NC 1024
#define NH 16
#define ND 64
#define MTOT (NB*NT)   // 4096

// Scratch
__device__ float g_q[NB*NH*NT*ND];
__device__ float g_k[NB*NH*NT*ND];
__device__ float g_v[NB*NH*NT*ND];
__device__ float g_y[NB*NT*NC];

__device__ __forceinline__ unsigned f2tf(float f) {
    unsigned r;
    asm("cvt.rna.tf32.f32 %0, %1;" : "=r"(r) : "f"(f));
    return r;
}

__device__ __forceinline__ unsigned smem_u32(const void* p) {
    unsigned r;
    asm("{ .reg .u64 t; cvta.to.shared.u64 t, %1; cvt.u32.u64 %0, t; }"
        : "=r"(r) : "l"(p));
    return r;
}

__device__ __forceinline__ void ldsm4(unsigned& r0, unsigned& r1,
                                      unsigned& r2, unsigned& r3,
                                      const unsigned* p)
{
    unsigned a = smem_u32(p);
    asm volatile("ldmatrix.sync.aligned.m8n8.x4.shared.b16 {%0,%1,%2,%3}, [%4];"
                 : "=r"(r0), "=r"(r1), "=r"(r2), "=r"(r3) : "r"(a));
}

__device__ __forceinline__ void mma_tf32(float c[4], unsigned a0, unsigned a1,
                                         unsigned a2, unsigned a3,
                                         unsigned b0, unsigned b1)
{
    asm volatile(
        "mma.sync.aligned.m16n8k8.row.col.f32.tf32.tf32.f32 "
        "{%0,%1,%2,%3}, {%4,%5,%6,%7}, {%8,%9}, {%0,%1,%2,%3};"
        : "+f"(c[0]), "+f"(c[1]), "+f"(c[2]), "+f"(c[3])
        : "r"(a0), "r"(a1), "r"(a2), "r"(a3), "r"(b0), "r"(b1));
}

// ---------------------------------------------------------------------------
// TF32 tensor-core NT GEMM, ldmatrix fragment loads.
// Block 256 threads (8 warps, 4x2), tile 128x64, BK=32.
// ---------------------------------------------------------------------------
#define GBM 128
#define GBN 64
#define GBK 32
#define GSA 36   // (36r+c)%32 = (4r+c)%32 -> 8 LDSM rows hit distinct banks

__device__ __forceinline__ void gemm_tc(const float* __restrict__ A,
                                        const float* __restrict__ W,
                                        float C[2][4][4], int m0, int n0)
{
    __shared__ unsigned As[GBM * GSA];
    __shared__ unsigned Ws[GBN * GSA];

    const int tid  = threadIdx.x;
    const int wid  = tid >> 5;
    const int lane = tid & 31;
    const int wr   = wid >> 1;   // m offset wr*32
    const int wc   = wid & 1;    // n offset wc*32

    // LDSM lane-derived offsets
    const int aRow = (lane & 15);
    const int aCol = (lane >> 4) << 2;                       // 0 or 4
    const int bRow = (((lane >> 4) & 1) << 3) + (lane & 7);  // 0..15
    const int bCol = ((lane >> 3) & 1) << 2;                 // 0 or 4

    const int ar  = tid >> 3;    // 0..31 (+ i*32)
    const int ac4 = tid & 7;     // float4 column

    const float* Aptr = A + (size_t)(m0 + ar) * NC + ac4 * 4;
    const float* Wptr = W + (size_t)(n0 + ar) * NC + ac4 * 4;

    float4 afetch[4], wfetch[2];
    #pragma unroll
    for (int i = 0; i < 4; i++) afetch[i] = *(const float4*)(Aptr + i * 32 * NC);
    #pragma unroll
    for (int i = 0; i < 2; i++) wfetch[i] = *(const float4*)(Wptr + i * 32 * NC);

    for (int k0 = 0; k0 < NC; k0 += GBK) {
        __syncthreads();
        #pragma unroll
        for (int i = 0; i < 4; i++) {
            uint4 u;
            u.x = f2tf(afetch[i].x); u.y = f2tf(afetch[i].y);
            u.z = f2tf(afetch[i].z); u.w = f2tf(afetch[i].w);
            *(uint4*)&As[(ar + i * 32) * GSA + ac4 * 4] = u;
        }
        #pragma unroll
        for (int i = 0; i < 2; i++) {
            uint4 u;
            u.x = f2tf(wfetch[i].x); u.y = f2tf(wfetch[i].y);
            u.z = f2tf(wfetch[i].z); u.w = f2tf(wfetch[i].w);
            *(uint4*)&Ws[(ar + i * 32) * GSA + ac4 * 4] = u;
        }
        __syncthreads();

        if (k0 + GBK < NC) {
            #pragma unroll
            for (int i = 0; i < 4; i++)
                afetch[i] = *(const float4*)(Aptr + i * 32 * NC + k0 + GBK);
            #pragma unroll
            for (int i = 0; i < 2; i++)
                wfetch[i] = *(const float4*)(Wptr + i * 32 * NC + k0 + GBK);
        }

        #pragma unroll
        for (int kk = 0; kk < GBK; kk += 8) {
            unsigned a[2][4], b[4][2];
            #pragma unroll
            for (int mt = 0; mt < 2; mt++)
                ldsm4(a[mt][0], a[mt][1], a[mt][2], a[mt][3],
                      &As[(wr * 32 + mt * 16 + aRow) * GSA + kk + aCol]);
            #pragma unroll
            for (int p = 0; p < 2; p++)
                ldsm4(b[2*p][0], b[2*p][1], b[2*p+1][0], b[2*p+1][1],
                      &Ws[(wc * 32 + p * 16 + bRow) * GSA + kk + bCol]);
            #pragma unroll
            for (int mt = 0; mt < 2; mt++)
                #pragma unroll
                for (int nt = 0; nt < 4; nt++)
                    mma_tf32(C[mt][nt], a[mt][0], a[mt][1], a[mt][2], a[mt][3],
                             b[nt][0], b[nt][1]);
        }
    }
}

// QKV projections (gridDim.z selects Q/K/V), head-split scatter store
__global__ __launch_bounds__(256)
void qkv_kernel(const float* __restrict__ x,
                const float* __restrict__ Wq, const float* __restrict__ bq,
                const float* __restrict__ Wk, const float* __restrict__ bk,
                const float* __restrict__ Wv, const float* __restrict__ bv)
{
    const float* W; const float* bias; float* Out;
    if (blockIdx.z == 0)      { W = Wq; bias = bq; Out = g_q; }
    else if (blockIdx.z == 1) { W = Wk; bias = bk; Out = g_k; }
    else                      { W = Wv; bias = bv; Out = g_v; }

    const int m0 = blockIdx.y * GBM;
    const int n0 = blockIdx.x * GBN;
    float C[2][4][4] = {};
    gemm_tc(x, W, C, m0, n0);

    const int lane = threadIdx.x & 31, wid = threadIdx.x >> 5;
    const int g = lane >> 2, t = lane & 3;
    const int wr = wid >> 1, wc = wid & 1;
    const int h = n0 >> 6;

    #pragma unroll
    for (int mt = 0; mt < 2; mt++) {
        #pragma unroll
        for (int rr = 0; rr < 2; rr++) {
            const int m = m0 + wr * 32 + mt * 16 + g + rr * 8;
            const int b = m >> 11;
            const int tt = m & (NT - 1);
            float* op = Out + (((size_t)(b * NH + h)) * NT + tt) * ND;
            #pragma unroll
            for (int nt = 0; nt < 4; nt++) {
                const int nl = wc * 32 + nt * 8 + 2 * t;
                float2 v;
                v.x = C[mt][nt][rr * 2 + 0] + bias[n0 + nl];
                v.y = C[mt][nt][rr * 2 + 1] + bias[n0 + nl + 1];
                *(float2*)(op + nl) = v;
            }
        }
    }
}

__global__ __launch_bounds__(256)
void proj_kernel(const float* __restrict__ Wp, const float* __restrict__ bp,
                 float* __restrict__ out)
{
    const int m0 = blockIdx.y * GBM;
    const int n0 = blockIdx.x * GBN;
    float C[2][4][4] = {};
    gemm_tc(g_y, Wp, C, m0, n0);

    const int lane = threadIdx.x & 31, wid = threadIdx.x >> 5;
    const int g = lane >> 2, t = lane & 3;
    const int wr = wid >> 1, wc = wid & 1;

    #pragma unroll
    for (int mt = 0; mt < 2; mt++) {
        #pragma unroll
        for (int rr = 0; rr < 2; rr++) {
            const int m = m0 + wr * 32 + mt * 16 + g + rr * 8;
            #pragma unroll
            for (int nt = 0; nt < 4; nt++) {
                const int n = n0 + wc * 32 + nt * 8 + 2 * t;
                float2 v;
                v.x = C[mt][nt][rr * 2 + 0] + bp[n];
                v.y = C[mt][nt][rr * 2 + 1] + bp[n + 1];
                *(float2*)(out + (size_t)m * NC + n) = v;
            }
        }
    }
}

// ---------------------------------------------------------------------------
// Tensor-core flash attention: 256 threads / 8 warps / 128 q-rows per block.
// K staged [key][d]; V staged TRANSPOSED [d][key]; P in its own buffer.
// All fragments via ldmatrix. 2 __syncthreads per tile.
// ---------------------------------------------------------------------------
#define APD 68   // (68r+c)%32 = (4r+c)%32 -> LDSM rows conflict-free; 272B row pitch

#define ATT_SMEM_WORDS (64*APD + 64*APD + 128*APD)

__global__ __launch_bounds__(256)
void attn_kernel()
{
    extern __shared__ unsigned sm[];
    unsigned* Ks = sm;                 // [64][APD]  key-major K tile (tf32)
    unsigned* Vt = sm + 64 * APD;      // [64][APD]  d-major (transposed) V tile
    unsigned* Ps = sm + 128 * APD;     // [128][APD] P tile (tf32)

    const int tid  = threadIdx.x;
    const int wid  = tid >> 5;
    const int lane = tid & 31;
    const int g    = lane >> 2;
    const int t    = lane & 3;

    const int bh = blockIdx.y;
    const int qb = gridDim.x - 1 - blockIdx.x;   // heavy blocks first
    const int q0 = qb * 128;
    const int rb = wid * 16;                     // warp's local row base

    // LDSM lane-derived offsets (B-pattern and A-pattern)
    const int bRow = (((lane >> 4) & 1) << 3) + (lane & 7);
    const int bCol = ((lane >> 3) & 1) << 2;
    const int aRow = lane & 15;
    const int aCol = (lane >> 4) << 2;

    // ---- Q fragments straight from gmem (pre-scaled 1/8, tf32) ----
    unsigned Qf[8][4];
    {
        const float* qp = g_q + ((size_t)bh * NT + q0 + rb) * ND;
        #pragma unroll
        for (int kt = 0; kt < 8; kt++) {
            Qf[kt][0] = f2tf(qp[(g)     * ND + kt * 8 + t]     * 0.125f);
            Qf[kt][1] = f2tf(qp[(g + 8) * ND + kt * 8 + t]     * 0.125f);
            Qf[kt][2] = f2tf(qp[(g)     * ND + kt * 8 + t + 4] * 0.125f);
            Qf[kt][3] = f2tf(qp[(g + 8) * ND + kt * 8 + t + 4] * 0.125f);
        }
    }

    float Of[8][4];
    #pragma unroll
    for (int nt = 0; nt < 8; nt++)
        #pragma unroll
        for (int j = 0; j < 4; j++) Of[nt][j] = 0.f;
    float mrow[2] = {-1e30f, -1e30f};
    float lrow[2] = {0.f, 0.f};

    // staging indices
    const int kr  = tid >> 2;          // K: row (key), 0..63
    const int kc  = (tid & 3) << 4;    // K: 16-col group
    const int vr  = lane + ((wid & 1) << 5);   // V: source row (key), 0..63
    const int vcg = (wid >> 1) << 4;           // V: 16-col group (d)

    const float* kbase = g_k + (size_t)bh * NT * ND;
    const float* vbase = g_v + (size_t)bh * NT * ND;

    const int ntiles = 2 * qb + 2;

    for (int kt0 = 0; kt0 < ntiles; kt0++) {
        // ---- stage K [key][d] (STS.128) and V transposed [d][key] ----
        {
            const float* kp = kbase + ((size_t)(kt0 * 64 + kr)) * ND + kc;
            #pragma unroll
            for (int i = 0; i < 4; i++) {
                float4 v = *(const float4*)(kp + i * 4);
                uint4 u;
                u.x = f2tf(v.x); u.y = f2tf(v.y); u.z = f2tf(v.z); u.w = f2tf(v.w);
                *(uint4*)&Ks[kr * APD + kc + i * 4] = u;
            }
            const float* vp = vbase + ((size_t)(kt0 * 64 + vr)) * ND + vcg;
            #pragma unroll
            for (int i = 0; i < 4; i++) {
                float4 v = *(const float4*)(vp + i * 4);
                Vt[(vcg + i * 4 + 0) * APD + vr] = f2tf(v.x);
                Vt[(vcg + i * 4 + 1) * APD + vr] = f2tf(v.y);
                Vt[(vcg + i * 4 + 2) * APD + vr] = f2tf(v.z);
                Vt[(vcg + i * 4 + 3) * APD + vr] = f2tf(v.w);
            }
        }
        __syncthreads();

        // warps whose rows are entirely left of this key tile skip compute
        const bool active = (kt0 * 64) <= (q0 + rb + 15);
        if (active) {
            // ---- S = Q K^T ----
            float Sf[8][4];
            #pragma unroll
            for (int nt = 0; nt < 8; nt++)
                #pragma unroll
                for (int j = 0; j < 4; j++) Sf[nt][j] = 0.f;

            #pragma unroll
            for (int kt = 0; kt < 8; kt++) {
                unsigned b[8][2];
                #pragma unroll
                for (int p = 0; p < 4; p++)
                    ldsm4(b[2*p][0], b[2*p][1], b[2*p+1][0], b[2*p+1][1],
                          &Ks[(p * 16 + bRow) * APD + kt * 8 + bCol]);
                #pragma unroll
                for (int nt = 0; nt < 8; nt++)
                    mma_tf32(Sf[nt], Qf[kt][0], Qf[kt][1], Qf[kt][2], Qf[kt][3],
                             b[nt][0], b[nt][1]);
            }

            // ---- causal mask (only the two diagonal tiles) ----
            if (kt0 >= 2 * qb) {
                #pragma unroll
                for (int nt = 0; nt < 8; nt++)
                    #pragma unroll
                    for (int j = 0; j < 4; j++) {
                        const int key = kt0 * 64 + nt * 8 + 2 * t + (j & 1);
                        const int qr  = q0 + rb + g + (j >> 1) * 8;
                        if (key > qr) Sf[nt][j] = -1e30f;
                    }
            }

            // ---- online softmax ----
            #pragma unroll
            for (int r = 0; r < 2; r++) {
                float rm = -1e30f;
                #pragma unroll
                for (int nt = 0; nt < 8; nt++) {
                    rm = fmaxf(rm, Sf[nt][2 * r]);
                    rm = fmaxf(rm, Sf[nt][2 * r + 1]);
                }
                rm = fmaxf(rm, __shfl_xor_sync(0xffffffff, rm, 1));
                rm = fmaxf(rm, __shfl_xor_sync(0xffffffff, rm, 2));
                const float mn   = fmaxf(mrow[r], rm);
                const float corr = __expf(mrow[r] - mn);
                mrow[r] = mn;
                float rs = 0.f;
                #pragma unroll
                for (int nt = 0; nt < 8; nt++) {
                    const float p0 = __expf(Sf[nt][2 * r]     - mn);
                    const float p1 = __expf(Sf[nt][2 * r + 1] - mn);
                    Sf[nt][2 * r] = p0; Sf[nt][2 * r + 1] = p1;
                    rs += p0 + p1;
                }
                rs += __shfl_xor_sync(0xffffffff, rs, 1);
                rs += __shfl_xor_sync(0xffffffff, rs, 2);
                lrow[r] = lrow[r] * corr + rs;
                #pragma unroll
                for (int nt = 0; nt < 8; nt++) {
                    Of[nt][2 * r]     *= corr;
                    Of[nt][2 * r + 1] *= corr;
                }
            }

            // ---- write P (STS.64 pairs) into this warp's slice ----
            #pragma unroll
            for (int nt = 0; nt < 8; nt++) {
                uint2 u0; u0.x = f2tf(Sf[nt][0]); u0.y = f2tf(Sf[nt][1]);
                *(uint2*)&Ps[(rb + g)     * APD + nt * 8 + 2 * t] = u0;
                uint2 u1; u1.x = f2tf(Sf[nt][2]); u1.y = f2tf(Sf[nt][3]);
                *(uint2*)&Ps[(rb + g + 8) * APD + nt * 8 + 2 * t] = u1;
            }
            __syncwarp();

            // ---- O += P V ----
            #pragma unroll
            for (int kt = 0; kt < 8; kt++) {
                unsigned a0, a1, a2, a3;
                ldsm4(a0, a1, a2, a3, &Ps[(rb + aRow) * APD + kt * 8 + aCol]);
                unsigned b[8][2];
                #pragma unroll
                for (int p = 0; p < 4; p++)
                    ldsm4(b[2*p][0], b[2*p][1], b[2*p+1][0], b[2*p+1][1],
                          &Vt[(p * 16 + bRow) * APD + kt * 8 + bCol]);
                #pragma unroll
                for (int nt = 0; nt < 8; nt++)
                    mma_tf32(Of[nt], a0, a1, a2, a3, b[nt][0], b[nt][1]);
            }
        }
        __syncthreads();   // K/V/P reads done before next tile overwrites
    }

    // ---- epilogue: divide by l, scatter to g_y [b, t, h*64+d] ----
    const float inv0 = 1.0f / lrow[0];
    const float inv1 = 1.0f / lrow[1];
    const int b = bh >> 4;
    const int h = bh & 15;
    float* yp = g_y + ((size_t)(b * NT) + q0 + rb) * NC + h * ND;

    #pragma unroll
    for (int nt = 0; nt < 8; nt++) {
        const int c = nt * 8 + 2 * t;
        float2 v0; v0.x = Of[nt][0] * inv0; v0.y = Of[nt][1] * inv0;
        *(float2*)(yp + (size_t)g * NC + c) = v0;
        float2 v1; v1.x = Of[nt][2] * inv1; v1.y = Of[nt][3] * inv1;
        *(float2*)(yp + (size_t)(g + 8) * NC + c) = v1;
    }
}

// ---------------------------------------------------------------------------
extern "C" void kernel_launch(void* const* d_in, const int* in_sizes, int n_in,
                              void* d_out, int out_size)
{
    const float* x  = (const float*)d_in[0];
    const float* Wk = (const float*)d_in[1];
    const float* bk = (const float*)d_in[2];
    const float* Wq = (const float*)d_in[3];
    const float* bq = (const float*)d_in[4];
    const float* Wv = (const float*)d_in[5];
    const float* bv = (const float*)d_in[6];
    const float* Wp = (const float*)d_in[7];
    const float* bp = (const float*)d_in[8];
    float* out = (float*)d_out;

    cudaFuncSetAttribute(attn_kernel,
                         cudaFuncAttributeMaxDynamicSharedMemorySize,
                         ATT_SMEM_WORDS * 4);

    dim3 gq(NC / GBN, MTOT / GBM, 3);
    qkv_kernel<<<gq, 256>>>(x, Wq, bq, Wk, bk, Wv, bv);

    dim3 ga(NT / 128, NB * NH);
    attn_kernel<<<ga, 256, ATT_SMEM_WORDS * 4>>>();

    dim3 gp(NC / GBN, MTOT / GBM);
    proj_kernel<<<gp, 256>>>(Wp, bp, out);
}